// round 5
// baseline (speedup 1.0000x reference)
#include <cuda_runtime.h>
#include <math.h>
#include <stdint.h>

// ---------------- problem constants ----------------
#define D128 128
#define BGR 64
#define NPG0 1024
#define NMAX (BGR * NPG0)        // 65536
#define EMAX 1048576
#define K1 820                   // ceil(0.8*1024)
#define K2 656                   // ceil(0.8*820)
#define K3 525                   // ceil(0.8*656)

// ---------------- scratch (device globals; no allocations allowed) ----------------
__device__ float  g_mean[NMAX * D128];
__device__ float  g_h[NMAX * D128];
__device__ float  g_poolA[BGR * K1 * D128];
__device__ float  g_poolB[BGR * K2 * D128];
__device__ float  g_score[NMAX];
__device__ int    g_newid[NMAX];
__device__ int    g_orig2cur[NMAX];
__device__ int    g_cur2orig[NMAX];
__device__ int    g_deg[NMAX];
__device__ int    g_cursor[NMAX];
__device__ int    g_rowptr[NMAX + 1];
__device__ int    g_nbr[EMAX];
__device__ int    g_part[64];
__device__ int    g_offs[64];
__device__ float2 g_bsplit[256 * D128];   // interleaved {hi, lo} of [Wl;Wr]
__device__ float  g_s[BGR * 256];

__device__ __forceinline__ void tf32_split(float v, uint32_t& hi, uint32_t& lo) {
    asm("cvt.rna.tf32.f32 %0, %1;" : "=r"(hi) : "f"(v));
    float r = v - __uint_as_float(hi);
    asm("cvt.rna.tf32.f32 %0, %1;" : "=r"(lo) : "f"(r));
}

__device__ __forceinline__ void mma_m16n8k8(float* c, const uint32_t* a, const uint32_t* b) {
    asm volatile(
        "mma.sync.aligned.m16n8k8.row.col.f32.tf32.tf32.f32 "
        "{%0,%1,%2,%3}, {%4,%5,%6,%7}, {%8,%9}, {%0,%1,%2,%3};"
        : "+f"(c[0]), "+f"(c[1]), "+f"(c[2]), "+f"(c[3])
        : "r"(a[0]), "r"(a[1]), "r"(a[2]), "r"(a[3]), "r"(b[0]), "r"(b[1]));
}

__device__ __forceinline__ uint32_t smem_u32(const void* p) {
    uint32_t a;
    asm("{ .reg .u64 t; cvta.to.shared.u64 t, %1; cvt.u32.u64 %0, t; }" : "=r"(a) : "l"(p));
    return a;
}

#define CP_ASYNC16(dst_u32, gptr) \
    asm volatile("cp.async.cg.shared.global [%0], [%1], 16;" :: "r"(dst_u32), "l"(gptr))
#define CP_COMMIT() asm volatile("cp.async.commit_group;" ::: "memory")
#define CP_WAIT(n)  asm volatile("cp.async.wait_group %0;" :: "n"(n) : "memory")

// ---------------- CSR build (once, on original graph) ----------------
__global__ void k_zero_int(int* p, int n) {
    int i = blockIdx.x * blockDim.x + threadIdx.x;
    if (i < n) p[i] = 0;
}

__global__ void k_count(const int* __restrict__ dst, int E, int* __restrict__ deg) {
    int e = blockIdx.x * blockDim.x + threadIdx.x;
    if (e < E) atomicAdd(&deg[dst[e]], 1);
}

__global__ void k_scan1(const int* __restrict__ deg, int* __restrict__ part) {
    __shared__ int s[1024];
    int t = threadIdx.x;
    s[t] = deg[blockIdx.x * 1024 + t];
    __syncthreads();
    for (int off = 512; off > 0; off >>= 1) {
        if (t < off) s[t] += s[t + off];
        __syncthreads();
    }
    if (t == 0) part[blockIdx.x] = s[0];
}

__global__ void k_scan2(const int* __restrict__ part, int* __restrict__ offs) {
    __shared__ int s[64];
    int t = threadIdx.x;
    int my = part[t];
    s[t] = my;
    __syncthreads();
    for (int off = 1; off < 64; off <<= 1) {
        int v = s[t];
        if (t >= off) v += s[t - off];
        __syncthreads();
        s[t] = v;
        __syncthreads();
    }
    offs[t] = s[t] - my;
}

__global__ void k_scan3(const int* __restrict__ deg, const int* __restrict__ offs,
                        int* __restrict__ rowptr, int* __restrict__ cursor, int n) {
    __shared__ int s[1024];
    int t = threadIdx.x;
    int i = blockIdx.x * 1024 + t;
    int my = deg[i];
    s[t] = my;
    __syncthreads();
    for (int off = 1; off < 1024; off <<= 1) {
        int v = s[t];
        if (t >= off) v += s[t - off];
        __syncthreads();
        s[t] = v;
        __syncthreads();
    }
    int ex = s[t] - my + offs[blockIdx.x];
    rowptr[i] = ex;
    cursor[i] = ex;
    if (blockIdx.x == 63 && t == 1023) rowptr[n] = ex + my;
}

__global__ void k_scatter(const int* __restrict__ src, const int* __restrict__ dst, int E,
                          int* __restrict__ cursor, int* __restrict__ nbr) {
    int e = blockIdx.x * blockDim.x + threadIdx.x;
    if (e < E) {
        int p = atomicAdd(&cursor[dst[e]], 1);
        nbr[p] = src[e];
    }
}

__global__ void k_initmaps(int* __restrict__ o2c, int* __restrict__ c2o) {
    int i = blockIdx.x * blockDim.x + threadIdx.x;
    if (i < NMAX) { o2c[i] = i; c2o[i] = i; }
}

__global__ void k_compose(int* __restrict__ o2c, int* __restrict__ c2o,
                          const int* __restrict__ newid) {
    int o = blockIdx.x * blockDim.x + threadIdx.x;
    if (o >= NMAX) return;
    int c = o2c[o];
    int nc = (c >= 0) ? newid[c] : -1;
    o2c[o] = nc;
    if (nc >= 0) c2o[nc] = o;
}

// ---------------- mean aggregation over reusable original CSR ----------------
__global__ void k_aggregate(const float* __restrict__ X, const int* __restrict__ rowptr,
                            const int* __restrict__ nbr, const int* __restrict__ c2o,
                            const int* __restrict__ o2c, float* __restrict__ mean, int n) {
    int w = (blockIdx.x * blockDim.x + threadIdx.x) >> 5;
    int lane = threadIdx.x & 31;
    if (w >= n) return;
    int o = c2o[w];
    int b = rowptr[o], e = rowptr[o + 1];
    float4 acc = make_float4(0.f, 0.f, 0.f, 0.f);
    float cnt = 0.f;
#pragma unroll 4
    for (int j = b; j < e; j++) {
        int c = o2c[nbr[j]];
        float wgt = (c >= 0) ? 1.f : 0.f;
        int idx = (c >= 0) ? c : 0;
        float4 v = ((const float4*)(X + (size_t)idx * D128))[lane];
        acc.x += wgt * v.x; acc.y += wgt * v.y;
        acc.z += wgt * v.z; acc.w += wgt * v.w;
        cnt += wgt;
    }
    float inv = 1.0f / fmaxf(cnt, 1.f);
    acc.x *= inv; acc.y *= inv; acc.z *= inv; acc.w *= inv;
    ((float4*)(mean + (size_t)w * D128))[lane] = acc;
}

// ---------------- weight pre-split: [Wl;Wr] -> interleaved {hi,lo} float2 ----------------
__global__ void k_splitB(const float* __restrict__ Wl, const float* __restrict__ Wr,
                         float2* __restrict__ bs) {
    int i = blockIdx.x * blockDim.x + threadIdx.x;   // 32768
    float v = (i < 16384) ? Wl[i] : Wr[i - 16384];
    uint32_t hi, lo;
    tf32_split(v, hi, lo);
    bs[i] = make_float2(__uint_as_float(hi), __uint_as_float(lo));
}

// ---------------- tf32 mma GEMM v2: H = relu([mean|x] @ [Wl;Wr] + bl) ----------------
// CTA 128x128, K=256 in 16 chunks of 16.
// A: reg-prefetched, split at store into float2{hi,lo}, stride 20 float2.
// B: pre-split global, cp.async double-buffered, stride 132 float2.
#define AS2 20
#define BS2 132
#define GEMM_SMEM ((128 * AS2 + 2 * 16 * BS2) * 8)

__global__ void __launch_bounds__(256, 2)
k_gemm_v2(const float* __restrict__ Am, const float* __restrict__ Ax,
          const float2* __restrict__ Bs, const float* __restrict__ bias,
          float* __restrict__ H, int n) {
    extern __shared__ float2 smem2[];
    float2* A2 = smem2;                       // 128 * AS2
    float2* B2 = smem2 + 128 * AS2;           // 2 * 16 * BS2
    uint32_t b2u = smem_u32(B2);

    int t = threadIdx.x, lane = t & 31, wid = t >> 5;
    int wm = (wid >> 2) * 64;
    int wn = (wid & 3) * 32;
    int m0 = blockIdx.x * 128;

    float c[4][4][4];
#pragma unroll
    for (int i = 0; i < 4; i++)
#pragma unroll
        for (int j = 0; j < 4; j++)
#pragma unroll
            for (int r = 0; r < 4; r++) c[i][j][r] = 0.f;

    int arow = t >> 1;
    int acol0 = (t & 1) * 8;

    // B cp.async mapping: thread copies 4x16B; flat byte q-th = t*64 + q*16
    int bflat0 = t * 64;

    // ---- prologue: issue B chunk0, prefetch A chunk0 ----
#pragma unroll
    for (int q = 0; q < 4; q++) {
        int flat = bflat0 + q * 16;
        int row = flat >> 10;
        int col2 = (flat & 1023) >> 3;
        uint32_t dstu = b2u + (uint32_t)(row * BS2 + col2) * 8u;
        CP_ASYNC16(dstu, (const char*)Bs + flat);
    }
    CP_COMMIT();
    float4 pa0, pa1;
    {
        const float* A = Am + (size_t)(m0 + arow) * D128 + acol0;
        pa0 = *(const float4*)A;
        pa1 = *(const float4*)(A + 4);
    }

    for (int ch = 0; ch < 16; ch++) {
        __syncthreads();   // previous compute done reading A2 / B buf
        // store A (split into interleaved float2)
        {
            float av[8] = {pa0.x, pa0.y, pa0.z, pa0.w, pa1.x, pa1.y, pa1.z, pa1.w};
            float2* dst = A2 + arow * AS2 + acol0;
#pragma unroll
            for (int e = 0; e < 8; e++) {
                uint32_t hi, lo;
                tf32_split(av[e], hi, lo);
                dst[e] = make_float2(__uint_as_float(hi), __uint_as_float(lo));
            }
        }
        // issue next B chunk
        if (ch < 15) {
            const char* gsrc = (const char*)(Bs + (ch + 1) * 2048);
            uint32_t bufu = b2u + (uint32_t)(((ch + 1) & 1) * 16 * BS2) * 8u;
#pragma unroll
            for (int q = 0; q < 4; q++) {
                int flat = bflat0 + q * 16;
                int row = flat >> 10;
                int col2 = (flat & 1023) >> 3;
                CP_ASYNC16(bufu + (uint32_t)(row * BS2 + col2) * 8u, gsrc + flat);
            }
            CP_COMMIT();
            CP_WAIT(1);   // current chunk's B resident
        } else {
            CP_WAIT(0);
        }
        __syncthreads();
        // prefetch next A chunk
        if (ch < 15) {
            int nc = ch + 1;
            const float* A = (nc < 8)
                ? Am + (size_t)(m0 + arow) * D128 + nc * 16 + acol0
                : Ax + (size_t)(m0 + arow) * D128 + (nc - 8) * 16 + acol0;
            pa0 = *(const float4*)A;
            pa1 = *(const float4*)(A + 4);
        }
        // compute on A2 + B buf[ch&1]
        const float2* Bbuf = B2 + (ch & 1) * 16 * BS2;
#pragma unroll
        for (int ks = 0; ks < 2; ks++) {
            uint32_t bh[4][2], blo[4][2];
#pragma unroll
            for (int nf = 0; nf < 4; nf++)
#pragma unroll
                for (int r = 0; r < 2; r++) {
                    float2 b = Bbuf[(ks * 8 + (lane & 3) + 4 * r) * BS2 + wn + nf * 8 + (lane >> 2)];
                    bh[nf][r] = __float_as_uint(b.x);
                    blo[nf][r] = __float_as_uint(b.y);
                }
#pragma unroll
            for (int mf = 0; mf < 4; mf++) {
                uint32_t ah[4], al[4];
#pragma unroll
                for (int r = 0; r < 4; r++) {
                    float2 a = A2[(wm + mf * 16 + (lane >> 2) + 8 * (r & 1)) * AS2
                                  + ks * 8 + (lane & 3) + 4 * (r >> 1)];
                    ah[r] = __float_as_uint(a.x);
                    al[r] = __float_as_uint(a.y);
                }
#pragma unroll
                for (int nf = 0; nf < 4; nf++) {
                    mma_m16n8k8(c[mf][nf], ah, bh[nf]);
                    mma_m16n8k8(c[mf][nf], ah, blo[nf]);
                    mma_m16n8k8(c[mf][nf], al, bh[nf]);
                }
            }
        }
    }

    // epilogue: bias + relu
    int r0 = lane >> 2, cq = (lane & 3) * 2;
#pragma unroll
    for (int mf = 0; mf < 4; mf++) {
        int row = m0 + wm + mf * 16 + r0;
#pragma unroll
        for (int nf = 0; nf < 4; nf++) {
            int col = wn + nf * 8 + cq;
            float b0 = bias[col], b1 = bias[col + 1];
            float2 o0, o1;
            o0.x = fmaxf(c[mf][nf][0] + b0, 0.f);
            o0.y = fmaxf(c[mf][nf][1] + b1, 0.f);
            o1.x = fmaxf(c[mf][nf][2] + b0, 0.f);
            o1.y = fmaxf(c[mf][nf][3] + b1, 0.f);
            *(float2*)(H + (size_t)row * D128 + col) = o0;
            *(float2*)(H + (size_t)(row + 8) * D128 + col) = o1;
        }
    }
}

// score[i] = tanh(h_i . pw / ||pw||), one warp per row
__global__ void k_score(const float* __restrict__ H, const float* __restrict__ pw,
                        float* __restrict__ score, int n) {
    int w = (blockIdx.x * blockDim.x + threadIdx.x) >> 5;
    int lane = threadIdx.x & 31;
    if (w >= n) return;
    float4 h4 = ((const float4*)(H + (size_t)w * D128))[lane];
    float4 w4 = ((const float4*)pw)[lane];
    float dot = h4.x * w4.x + h4.y * w4.y + h4.z * w4.z + h4.w * w4.w;
    float nn = w4.x * w4.x + w4.y * w4.y + w4.z * w4.z + w4.w * w4.w;
#pragma unroll
    for (int off = 16; off > 0; off >>= 1) {
        dot += __shfl_xor_sync(0xFFFFFFFF, dot, off);
        nn  += __shfl_xor_sync(0xFFFFFFFF, nn, off);
    }
    if (lane == 0) score[w] = tanhf(dot / sqrtf(nn));
}

// per-graph bitonic top-K + fused pool write + readout (max||mean accumulate)
__global__ void k_topk(const float* __restrict__ score, const float* __restrict__ H,
                       float* __restrict__ pool, int* __restrict__ newid,
                       float* __restrict__ s_out, int Npg, int K, int round) {
    __shared__ float skey[1024];
    __shared__ int   sidx[1024];
    __shared__ float rmx[8][128];
    __shared__ float rsm[8][128];
    int g = blockIdx.x;
    int t = threadIdx.x;   // 1024 threads
    skey[t] = (t < Npg) ? score[g * Npg + t] : -INFINITY;
    sidx[t] = t;
    __syncthreads();
    for (int k = 2; k <= 1024; k <<= 1) {
        for (int j = k >> 1; j > 0; j >>= 1) {
            int ixj = t ^ j;
            if (ixj > t) {
                bool desc = ((t & k) == 0);
                float a = skey[t], b = skey[ixj];
                bool sw = desc ? (a < b) : (a > b);
                if (sw) {
                    skey[t] = b; skey[ixj] = a;
                    int tmp = sidx[t]; sidx[t] = sidx[ixj]; sidx[ixj] = tmp;
                }
            }
            __syncthreads();
        }
    }
    if (t < Npg) {
        int node = sidx[t];
        newid[g * Npg + node] = (t < K) ? (g * K + t) : -1;
    }
    __syncthreads();
    // fused pool write + per-feature max/sum
    int f = t & 127, part = t >> 7;     // 8 parts x 128 features
    float mx = -INFINITY, sm = 0.f;
    for (int r = part; r < K; r += 8) {
        int node = sidx[r];
        float v = H[(size_t)(g * Npg + node) * D128 + f] * skey[r];
        pool[(size_t)(g * K + r) * D128 + f] = v;
        mx = fmaxf(mx, v);
        sm += v;
    }
    rmx[part][f] = mx; rsm[part][f] = sm;
    __syncthreads();
    if (t < 128) {
        float m2 = rmx[0][f], s2 = rsm[0][f];
#pragma unroll
        for (int p = 1; p < 8; p++) {
            m2 = fmaxf(m2, rmx[p][f]);
            s2 += rsm[p][f];
        }
        float mean = s2 / (float)K;
        if (round == 0) {
            s_out[g * 256 + f] = m2;
            s_out[g * 256 + 128 + f] = mean;
        } else {
            s_out[g * 256 + f] += m2;
            s_out[g * 256 + 128 + f] += mean;
        }
    }
}

// final MLP: 256->128->64->1 + sigmoid
__global__ void k_mlp(const float* __restrict__ s,
                      const float* __restrict__ W1, const float* __restrict__ b1,
                      const float* __restrict__ W2, const float* __restrict__ b2,
                      const float* __restrict__ W3, const float* __restrict__ b3,
                      float* __restrict__ out) {
    __shared__ float sh[256];
    __shared__ float h1[128];
    __shared__ float h2[64];
    __shared__ float red[128];
    int g = blockIdx.x, t = threadIdx.x;
    sh[t] = s[g * 256 + t];
    sh[t + 128] = s[g * 256 + 128 + t];
    __syncthreads();
    float acc = b1[t];
    for (int k = 0; k < 256; k++) acc += sh[k] * W1[k * 128 + t];
    h1[t] = fmaxf(acc, 0.f);
    __syncthreads();
    if (t < 64) {
        float a = b2[t];
        for (int k = 0; k < 128; k++) a += h1[k] * W2[k * 64 + t];
        h2[t] = fmaxf(a, 0.f);
    }
    __syncthreads();
    red[t] = (t < 64) ? h2[t] * W3[t] : 0.f;
    __syncthreads();
    for (int off = 64; off > 0; off >>= 1) {
        if (t < off) red[t] += red[t + off];
        __syncthreads();
    }
    if (t == 0) out[g] = 1.f / (1.f + expf(-(red[0] + b3[0])));
}

// ---------------- host orchestration ----------------
extern "C" void kernel_launch(void* const* d_in, const int* in_sizes, int n_in,
                              void* d_out, int out_size) {
    const float* x   = (const float*)d_in[0];
    const int*   ei  = (const int*)d_in[1];
    const int E = in_sizes[1] / 2;

    const float* Wl1 = (const float*)d_in[2];
    const float* bl1 = (const float*)d_in[3];
    const float* Wr1 = (const float*)d_in[4];
    const float* pw1 = (const float*)d_in[5];
    const float* Wl2 = (const float*)d_in[6];
    const float* bl2 = (const float*)d_in[7];
    const float* Wr2 = (const float*)d_in[8];
    const float* pw2 = (const float*)d_in[9];
    const float* Wl3 = (const float*)d_in[10];
    const float* bl3 = (const float*)d_in[11];
    const float* Wr3 = (const float*)d_in[12];
    const float* pw3 = (const float*)d_in[13];
    const float* W1  = (const float*)d_in[14];
    const float* b1  = (const float*)d_in[15];
    const float* W2  = (const float*)d_in[16];
    const float* b2  = (const float*)d_in[17];
    const float* W3  = (const float*)d_in[18];
    const float* b3  = (const float*)d_in[19];

    float *meanP, *hP, *poolA, *poolB, *scoreP, *sP;
    float2* bsP;
    int *newidP, *o2cP, *c2oP, *degP, *curP, *rpP, *nbrP, *partP, *offsP;
    cudaGetSymbolAddress((void**)&meanP, g_mean);
    cudaGetSymbolAddress((void**)&hP, g_h);
    cudaGetSymbolAddress((void**)&poolA, g_poolA);
    cudaGetSymbolAddress((void**)&poolB, g_poolB);
    cudaGetSymbolAddress((void**)&scoreP, g_score);
    cudaGetSymbolAddress((void**)&sP, g_s);
    cudaGetSymbolAddress((void**)&bsP, g_bsplit);
    cudaGetSymbolAddress((void**)&newidP, g_newid);
    cudaGetSymbolAddress((void**)&o2cP, g_orig2cur);
    cudaGetSymbolAddress((void**)&c2oP, g_cur2orig);
    cudaGetSymbolAddress((void**)&degP, g_deg);
    cudaGetSymbolAddress((void**)&curP, g_cursor);
    cudaGetSymbolAddress((void**)&rpP, g_rowptr);
    cudaGetSymbolAddress((void**)&nbrP, g_nbr);
    cudaGetSymbolAddress((void**)&partP, g_part);
    cudaGetSymbolAddress((void**)&offsP, g_offs);

    static int attr_done = 0;
    if (!attr_done) {
        cudaFuncSetAttribute(k_gemm_v2, cudaFuncAttributeMaxDynamicSharedMemorySize, GEMM_SMEM);
        attr_done = 1;
    }

    const int TB = 256;
    const int EB = (E + TB - 1) / TB;
    const int n0 = NMAX;

    // ---- one-time CSR build on original graph ----
    k_zero_int<<<(n0 + TB - 1) / TB, TB>>>(degP, n0);
    k_count<<<EB, TB>>>(ei + E, E, degP);
    k_scan1<<<64, 1024>>>(degP, partP);
    k_scan2<<<1, 64>>>(partP, offsP);
    k_scan3<<<64, 1024>>>(degP, offsP, rpP, curP, n0);
    k_scatter<<<EB, TB>>>(ei, ei + E, E, curP, nbrP);
    k_initmaps<<<(n0 + TB - 1) / TB, TB>>>(o2cP, c2oP);

    struct LayerCfg {
        const float *xin, *Wl, *bl, *Wr, *pw;
        float* pool;
        int n, Npg, K, round;
    };
    LayerCfg layers[3] = {
        { x,     Wl1, bl1, Wr1, pw1, poolA, BGR * NPG0, NPG0, K1, 0 },
        { poolA, Wl2, bl2, Wr2, pw2, poolB, BGR * K1,   K1,   K2, 1 },
        { poolB, Wl3, bl3, Wr3, pw3, poolA, BGR * K2,   K2,   K3, 2 },
    };

    for (int L = 0; L < 3; L++) {
        LayerCfg& c = layers[L];
        int n = c.n;
        k_splitB<<<128, 256>>>(c.Wl, c.Wr, bsP);
        k_aggregate<<<(n * 32 + TB - 1) / TB, TB>>>(c.xin, rpP, nbrP, c2oP, o2cP, meanP, n);
        k_gemm_v2<<<n / 128, 256, GEMM_SMEM>>>(meanP, c.xin, bsP, c.bl, hP, n);
        k_score<<<(n * 32 + TB - 1) / TB, TB>>>(hP, c.pw, scoreP, n);
        k_topk<<<BGR, 1024>>>(scoreP, hP, c.pool, newidP, sP, c.Npg, c.K, c.round);
        if (L < 2) k_compose<<<(n0 + TB - 1) / TB, TB>>>(o2cP, c2oP, newidP);
    }

    k_mlp<<<BGR, 128>>>(sP, W1, b1, W2, b2, W3, b3, (float*)d_out);
}

// round 6
// speedup vs baseline: 1.1543x; 1.1543x over previous
#include <cuda_runtime.h>
#include <math.h>
#include <stdint.h>

// ---------------- problem constants ----------------
#define D128 128
#define BGR 64
#define NPG0 1024
#define NMAX (BGR * NPG0)        // 65536
#define EMAX 1048576
#define K1 820                   // ceil(0.8*1024)
#define K2 656                   // ceil(0.8*820)
#define K3 525                   // ceil(0.8*656)

// ---------------- scratch (device globals; no allocations allowed) ----------------
__device__ float g_mean[NMAX * D128];
__device__ float g_h[NMAX * D128];
__device__ float g_poolA[BGR * K1 * D128];
__device__ float g_poolB[BGR * K2 * D128];
__device__ float g_score[NMAX];
__device__ int   g_newid[NMAX];
__device__ int   g_orig2cur[NMAX];
__device__ int   g_cur2orig[NMAX];
__device__ int   g_deg[NMAX];
__device__ int   g_cursor[NMAX];
__device__ int   g_rowptr[NMAX + 1];
__device__ int   g_nbr[EMAX];
__device__ int   g_part[64];
__device__ int   g_offs[64];
__device__ float g_bhi[256 * D128];
__device__ float g_blo[256 * D128];
__device__ float g_s[BGR * 256];

__device__ __forceinline__ void tf32_split(float v, uint32_t& hi, uint32_t& lo) {
    asm("cvt.rna.tf32.f32 %0, %1;" : "=r"(hi) : "f"(v));
    float r = v - __uint_as_float(hi);
    asm("cvt.rna.tf32.f32 %0, %1;" : "=r"(lo) : "f"(r));
}

__device__ __forceinline__ void mma_m16n8k8(float* c, const uint32_t* a, const uint32_t* b) {
    asm volatile(
        "mma.sync.aligned.m16n8k8.row.col.f32.tf32.tf32.f32 "
        "{%0,%1,%2,%3}, {%4,%5,%6,%7}, {%8,%9}, {%0,%1,%2,%3};"
        : "+f"(c[0]), "+f"(c[1]), "+f"(c[2]), "+f"(c[3])
        : "r"(a[0]), "r"(a[1]), "r"(a[2]), "r"(a[3]), "r"(b[0]), "r"(b[1]));
}

// ---------------- CSR build (once, on original graph) ----------------
__global__ void k_zero_int(int* p, int n) {
    int i = blockIdx.x * blockDim.x + threadIdx.x;
    if (i < n) p[i] = 0;
}

__global__ void k_count(const int* __restrict__ dst, int E, int* __restrict__ deg) {
    int e = blockIdx.x * blockDim.x + threadIdx.x;
    if (e < E) atomicAdd(&deg[dst[e]], 1);
}

__global__ void k_scan1(const int* __restrict__ deg, int* __restrict__ part) {
    __shared__ int s[1024];
    int t = threadIdx.x;
    s[t] = deg[blockIdx.x * 1024 + t];
    __syncthreads();
    for (int off = 512; off > 0; off >>= 1) {
        if (t < off) s[t] += s[t + off];
        __syncthreads();
    }
    if (t == 0) part[blockIdx.x] = s[0];
}

__global__ void k_scan2(const int* __restrict__ part, int* __restrict__ offs) {
    __shared__ int s[64];
    int t = threadIdx.x;
    int my = part[t];
    s[t] = my;
    __syncthreads();
    for (int off = 1; off < 64; off <<= 1) {
        int v = s[t];
        if (t >= off) v += s[t - off];
        __syncthreads();
        s[t] = v;
        __syncthreads();
    }
    offs[t] = s[t] - my;
}

__global__ void k_scan3(const int* __restrict__ deg, const int* __restrict__ offs,
                        int* __restrict__ rowptr, int* __restrict__ cursor, int n) {
    __shared__ int s[1024];
    int t = threadIdx.x;
    int i = blockIdx.x * 1024 + t;
    int my = deg[i];
    s[t] = my;
    __syncthreads();
    for (int off = 1; off < 1024; off <<= 1) {
        int v = s[t];
        if (t >= off) v += s[t - off];
        __syncthreads();
        s[t] = v;
        __syncthreads();
    }
    int ex = s[t] - my + offs[blockIdx.x];
    rowptr[i] = ex;
    cursor[i] = ex;
    if (blockIdx.x == 63 && t == 1023) rowptr[n] = ex + my;
}

__global__ void k_scatter(const int* __restrict__ src, const int* __restrict__ dst, int E,
                          int* __restrict__ cursor, int* __restrict__ nbr) {
    int e = blockIdx.x * blockDim.x + threadIdx.x;
    if (e < E) {
        int p = atomicAdd(&cursor[dst[e]], 1);
        nbr[p] = src[e];
    }
}

__global__ void k_initmaps(int* __restrict__ o2c, int* __restrict__ c2o) {
    int i = blockIdx.x * blockDim.x + threadIdx.x;
    if (i < NMAX) { o2c[i] = i; c2o[i] = i; }
}

__global__ void k_compose(int* __restrict__ o2c, int* __restrict__ c2o,
                          const int* __restrict__ newid) {
    int o = blockIdx.x * blockDim.x + threadIdx.x;
    if (o >= NMAX) return;
    int c = o2c[o];
    int nc = (c >= 0) ? newid[c] : -1;
    o2c[o] = nc;
    if (nc >= 0) c2o[nc] = o;
}

// ---------------- mean aggregation ----------------
// Layer 1: identity maps — no indirection, no masks.
__global__ void k_aggregate1(const float* __restrict__ X, const int* __restrict__ rowptr,
                             const int* __restrict__ nbr, float* __restrict__ mean, int n) {
    int w = (blockIdx.x * blockDim.x + threadIdx.x) >> 5;
    int lane = threadIdx.x & 31;
    if (w >= n) return;
    int b = rowptr[w], e = rowptr[w + 1];
    float4 acc = make_float4(0.f, 0.f, 0.f, 0.f);
#pragma unroll 4
    for (int j = b; j < e; j++) {
        float4 v = ((const float4*)(X + (size_t)nbr[j] * D128))[lane];
        acc.x += v.x; acc.y += v.y; acc.z += v.z; acc.w += v.w;
    }
    int d = e - b;
    float inv = 1.0f / (float)(d > 0 ? d : 1);
    acc.x *= inv; acc.y *= inv; acc.z *= inv; acc.w *= inv;
    ((float4*)(mean + (size_t)w * D128))[lane] = acc;
}

// Layers 2/3: original CSR + survival maps, alive-masked.
__global__ void k_aggregate(const float* __restrict__ X, const int* __restrict__ rowptr,
                            const int* __restrict__ nbr, const int* __restrict__ c2o,
                            const int* __restrict__ o2c, float* __restrict__ mean, int n) {
    int w = (blockIdx.x * blockDim.x + threadIdx.x) >> 5;
    int lane = threadIdx.x & 31;
    if (w >= n) return;
    int o = c2o[w];
    int b = rowptr[o], e = rowptr[o + 1];
    float4 acc = make_float4(0.f, 0.f, 0.f, 0.f);
    float cnt = 0.f;
#pragma unroll 4
    for (int j = b; j < e; j++) {
        int c = o2c[nbr[j]];
        float wgt = (c >= 0) ? 1.f : 0.f;
        int idx = (c >= 0) ? c : 0;
        float4 v = ((const float4*)(X + (size_t)idx * D128))[lane];
        acc.x += wgt * v.x; acc.y += wgt * v.y;
        acc.z += wgt * v.z; acc.w += wgt * v.w;
        cnt += wgt;
    }
    float inv = 1.0f / fmaxf(cnt, 1.f);
    acc.x *= inv; acc.y *= inv; acc.z *= inv; acc.w *= inv;
    ((float4*)(mean + (size_t)w * D128))[lane] = acc;
}

// ---------------- weight pre-split: [Wl;Wr] -> tf32 hi/lo in global ----------------
__global__ void k_splitB(const float* __restrict__ Wl, const float* __restrict__ Wr,
                         float* __restrict__ bh, float* __restrict__ bl) {
    int i = blockIdx.x * blockDim.x + threadIdx.x;   // 32768
    float v = (i < 16384) ? Wl[i] : Wr[i - 16384];
    uint32_t hi, lo;
    tf32_split(v, hi, lo);
    bh[i] = __uint_as_float(hi);
    bl[i] = __uint_as_float(lo);
}

// ---------------- tf32 mma GEMM (R4 version): H = relu([mean|x] @ [Wl;Wr] + bl) ----------------
#define ACH 16
#define ASTR 20
#define BSTR 136

__global__ void __launch_bounds__(256, 2)
k_gemm_mma(const float* __restrict__ Am, const float* __restrict__ Ax,
           const float* __restrict__ Bhi, const float* __restrict__ Blo,
           const float* __restrict__ bias, float* __restrict__ H, int n) {
    __shared__ float Ah[128 * ASTR];
    __shared__ float Al[128 * ASTR];
    __shared__ float Bh[ACH * BSTR];
    __shared__ float Bl[ACH * BSTR];
    int t = threadIdx.x, lane = t & 31, wid = t >> 5;
    int wm = (wid >> 2) * 64;
    int wn = (wid & 3) * 32;
    int m0 = blockIdx.x * 128;

    float c[4][4][4];
#pragma unroll
    for (int i = 0; i < 4; i++)
#pragma unroll
        for (int j = 0; j < 4; j++)
#pragma unroll
            for (int r = 0; r < 4; r++) c[i][j][r] = 0.f;

    int arow = t >> 1, acol0 = (t & 1) * 8;
    int brow = t >> 4, bcol0 = (t & 15) * 8;

    for (int ch = 0; ch < 16; ch++) {
        const float* A = (ch < 8) ? Am + (size_t)m0 * D128 + ch * ACH
                                  : Ax + (size_t)m0 * D128 + (ch - 8) * ACH;
#pragma unroll
        for (int q = 0; q < 2; q++) {
            float4 v = *(const float4*)(A + (size_t)arow * D128 + acol0 + q * 4);
            uint32_t h0, h1, h2, h3, l0, l1, l2, l3;
            tf32_split(v.x, h0, l0); tf32_split(v.y, h1, l1);
            tf32_split(v.z, h2, l2); tf32_split(v.w, h3, l3);
            float4 hv = make_float4(__uint_as_float(h0), __uint_as_float(h1),
                                    __uint_as_float(h2), __uint_as_float(h3));
            float4 lv = make_float4(__uint_as_float(l0), __uint_as_float(l1),
                                    __uint_as_float(l2), __uint_as_float(l3));
            *(float4*)(Ah + arow * ASTR + acol0 + q * 4) = hv;
            *(float4*)(Al + arow * ASTR + acol0 + q * 4) = lv;
        }
#pragma unroll
        for (int q = 0; q < 2; q++) {
            *(float4*)(Bh + brow * BSTR + bcol0 + q * 4) =
                *(const float4*)(Bhi + (size_t)(ch * ACH + brow) * D128 + bcol0 + q * 4);
            *(float4*)(Bl + brow * BSTR + bcol0 + q * 4) =
                *(const float4*)(Blo + (size_t)(ch * ACH + brow) * D128 + bcol0 + q * 4);
        }
        __syncthreads();

#pragma unroll
        for (int ks = 0; ks < 2; ks++) {
            uint32_t ah[4][4], bh[4][2];
#pragma unroll
            for (int mf = 0; mf < 4; mf++)
#pragma unroll
                for (int r = 0; r < 4; r++)
                    ah[mf][r] = __float_as_uint(
                        Ah[(wm + mf * 16 + (lane >> 2) + 8 * (r & 1)) * ASTR
                           + ks * 8 + (lane & 3) + 4 * (r >> 1)]);
#pragma unroll
            for (int nf = 0; nf < 4; nf++)
#pragma unroll
                for (int r = 0; r < 2; r++)
                    bh[nf][r] = __float_as_uint(
                        Bh[(ks * 8 + (lane & 3) + 4 * r) * BSTR + wn + nf * 8 + (lane >> 2)]);
#pragma unroll
            for (int mf = 0; mf < 4; mf++)
#pragma unroll
                for (int nf = 0; nf < 4; nf++)
                    mma_m16n8k8(c[mf][nf], ah[mf], bh[nf]);
            {
                uint32_t blo[4][2];
#pragma unroll
                for (int nf = 0; nf < 4; nf++)
#pragma unroll
                    for (int r = 0; r < 2; r++)
                        blo[nf][r] = __float_as_uint(
                            Bl[(ks * 8 + (lane & 3) + 4 * r) * BSTR + wn + nf * 8 + (lane >> 2)]);
#pragma unroll
                for (int mf = 0; mf < 4; mf++)
#pragma unroll
                    for (int nf = 0; nf < 4; nf++)
                        mma_m16n8k8(c[mf][nf], ah[mf], blo[nf]);
            }
            {
                uint32_t al[4][4];
#pragma unroll
                for (int mf = 0; mf < 4; mf++)
#pragma unroll
                    for (int r = 0; r < 4; r++)
                        al[mf][r] = __float_as_uint(
                            Al[(wm + mf * 16 + (lane >> 2) + 8 * (r & 1)) * ASTR
                               + ks * 8 + (lane & 3) + 4 * (r >> 1)]);
#pragma unroll
                for (int mf = 0; mf < 4; mf++)
#pragma unroll
                    for (int nf = 0; nf < 4; nf++)
                        mma_m16n8k8(c[mf][nf], al[mf], bh[nf]);
            }
        }
        __syncthreads();
    }

    int r0 = lane >> 2, cq = (lane & 3) * 2;
#pragma unroll
    for (int mf = 0; mf < 4; mf++) {
        int row = m0 + wm + mf * 16 + r0;
#pragma unroll
        for (int nf = 0; nf < 4; nf++) {
            int col = wn + nf * 8 + cq;
            float b0 = bias[col], b1 = bias[col + 1];
            float2 o0, o1;
            o0.x = fmaxf(c[mf][nf][0] + b0, 0.f);
            o0.y = fmaxf(c[mf][nf][1] + b1, 0.f);
            o1.x = fmaxf(c[mf][nf][2] + b0, 0.f);
            o1.y = fmaxf(c[mf][nf][3] + b1, 0.f);
            *(float2*)(H + (size_t)row * D128 + col) = o0;
            *(float2*)(H + (size_t)(row + 8) * D128 + col) = o1;
        }
    }
}

// score[i] = tanh(h_i . pw / ||pw||), one warp per row
__global__ void k_score(const float* __restrict__ H, const float* __restrict__ pw,
                        float* __restrict__ score, int n) {
    int w = (blockIdx.x * blockDim.x + threadIdx.x) >> 5;
    int lane = threadIdx.x & 31;
    if (w >= n) return;
    float4 h4 = ((const float4*)(H + (size_t)w * D128))[lane];
    float4 w4 = ((const float4*)pw)[lane];
    float dot = h4.x * w4.x + h4.y * w4.y + h4.z * w4.z + h4.w * w4.w;
    float nn = w4.x * w4.x + w4.y * w4.y + w4.z * w4.z + w4.w * w4.w;
#pragma unroll
    for (int off = 16; off > 0; off >>= 1) {
        dot += __shfl_xor_sync(0xFFFFFFFF, dot, off);
        nn  += __shfl_xor_sync(0xFFFFFFFF, nn, off);
    }
    if (lane == 0) score[w] = tanhf(dot / sqrtf(nn));
}

// per-graph bitonic top-K + fused pool write + readout (max||mean accumulate)
__global__ void k_topk(const float* __restrict__ score, const float* __restrict__ H,
                       float* __restrict__ pool, int* __restrict__ newid,
                       float* __restrict__ s_out, int Npg, int K, int round) {
    __shared__ float skey[1024];
    __shared__ int   sidx[1024];
    __shared__ float rmx[8][128];
    __shared__ float rsm[8][128];
    int g = blockIdx.x;
    int t = threadIdx.x;   // 1024 threads
    skey[t] = (t < Npg) ? score[g * Npg + t] : -INFINITY;
    sidx[t] = t;
    __syncthreads();
    for (int k = 2; k <= 1024; k <<= 1) {
        for (int j = k >> 1; j > 0; j >>= 1) {
            int ixj = t ^ j;
            if (ixj > t) {
                bool desc = ((t & k) == 0);
                float a = skey[t], b = skey[ixj];
                bool sw = desc ? (a < b) : (a > b);
                if (sw) {
                    skey[t] = b; skey[ixj] = a;
                    int tmp = sidx[t]; sidx[t] = sidx[ixj]; sidx[ixj] = tmp;
                }
            }
            __syncthreads();
        }
    }
    if (t < Npg) {
        int node = sidx[t];
        newid[g * Npg + node] = (t < K) ? (g * K + t) : -1;
    }
    __syncthreads();
    int f = t & 127, part = t >> 7;     // 8 parts x 128 features
    float mx = -INFINITY, sm = 0.f;
    for (int r = part; r < K; r += 8) {
        int node = sidx[r];
        float v = H[(size_t)(g * Npg + node) * D128 + f] * skey[r];
        pool[(size_t)(g * K + r) * D128 + f] = v;
        mx = fmaxf(mx, v);
        sm += v;
    }
    rmx[part][f] = mx; rsm[part][f] = sm;
    __syncthreads();
    if (t < 128) {
        float m2 = rmx[0][f], s2 = rsm[0][f];
#pragma unroll
        for (int p = 1; p < 8; p++) {
            m2 = fmaxf(m2, rmx[p][f]);
            s2 += rsm[p][f];
        }
        float mean = s2 / (float)K;
        if (round == 0) {
            s_out[g * 256 + f] = m2;
            s_out[g * 256 + 128 + f] = mean;
        } else {
            s_out[g * 256 + f] += m2;
            s_out[g * 256 + 128 + f] += mean;
        }
    }
}

// final MLP: 256->128->64->1 + sigmoid
__global__ void k_mlp(const float* __restrict__ s,
                      const float* __restrict__ W1, const float* __restrict__ b1,
                      const float* __restrict__ W2, const float* __restrict__ b2,
                      const float* __restrict__ W3, const float* __restrict__ b3,
                      float* __restrict__ out) {
    __shared__ float sh[256];
    __shared__ float h1[128];
    __shared__ float h2[64];
    __shared__ float red[128];
    int g = blockIdx.x, t = threadIdx.x;
    sh[t] = s[g * 256 + t];
    sh[t + 128] = s[g * 256 + 128 + t];
    __syncthreads();
    float acc = b1[t];
    for (int k = 0; k < 256; k++) acc += sh[k] * W1[k * 128 + t];
    h1[t] = fmaxf(acc, 0.f);
    __syncthreads();
    if (t < 64) {
        float a = b2[t];
        for (int k = 0; k < 128; k++) a += h1[k] * W2[k * 64 + t];
        h2[t] = fmaxf(a, 0.f);
    }
    __syncthreads();
    red[t] = (t < 64) ? h2[t] * W3[t] : 0.f;
    __syncthreads();
    for (int off = 64; off > 0; off >>= 1) {
        if (t < off) red[t] += red[t + off];
        __syncthreads();
    }
    if (t == 0) out[g] = 1.f / (1.f + expf(-(red[0] + b3[0])));
}

// ---------------- host orchestration ----------------
extern "C" void kernel_launch(void* const* d_in, const int* in_sizes, int n_in,
                              void* d_out, int out_size) {
    const float* x   = (const float*)d_in[0];
    const int*   ei  = (const int*)d_in[1];
    const int E = in_sizes[1] / 2;

    const float* Wl1 = (const float*)d_in[2];
    const float* bl1 = (const float*)d_in[3];
    const float* Wr1 = (const float*)d_in[4];
    const float* pw1 = (const float*)d_in[5];
    const float* Wl2 = (const float*)d_in[6];
    const float* bl2 = (const float*)d_in[7];
    const float* Wr2 = (const float*)d_in[8];
    const float* pw2 = (const float*)d_in[9];
    const float* Wl3 = (const float*)d_in[10];
    const float* bl3 = (const float*)d_in[11];
    const float* Wr3 = (const float*)d_in[12];
    const float* pw3 = (const float*)d_in[13];
    const float* W1  = (const float*)d_in[14];
    const float* b1  = (const float*)d_in[15];
    const float* W2  = (const float*)d_in[16];
    const float* b2  = (const float*)d_in[17];
    const float* W3  = (const float*)d_in[18];
    const float* b3  = (const float*)d_in[19];

    float *meanP, *hP, *poolA, *poolB, *scoreP, *sP, *bhiP, *bloP;
    int *newidP, *o2cP, *c2oP, *degP, *curP, *rpP, *nbrP, *partP, *offsP;
    cudaGetSymbolAddress((void**)&meanP, g_mean);
    cudaGetSymbolAddress((void**)&hP, g_h);
    cudaGetSymbolAddress((void**)&poolA, g_poolA);
    cudaGetSymbolAddress((void**)&poolB, g_poolB);
    cudaGetSymbolAddress((void**)&scoreP, g_score);
    cudaGetSymbolAddress((void**)&sP, g_s);
    cudaGetSymbolAddress((void**)&bhiP, g_bhi);
    cudaGetSymbolAddress((void**)&bloP, g_blo);
    cudaGetSymbolAddress((void**)&newidP, g_newid);
    cudaGetSymbolAddress((void**)&o2cP, g_orig2cur);
    cudaGetSymbolAddress((void**)&c2oP, g_cur2orig);
    cudaGetSymbolAddress((void**)&degP, g_deg);
    cudaGetSymbolAddress((void**)&curP, g_cursor);
    cudaGetSymbolAddress((void**)&rpP, g_rowptr);
    cudaGetSymbolAddress((void**)&nbrP, g_nbr);
    cudaGetSymbolAddress((void**)&partP, g_part);
    cudaGetSymbolAddress((void**)&offsP, g_offs);

    const int TB = 256;
    const int EB = (E + TB - 1) / TB;
    const int n0 = NMAX;

    // ---- one-time CSR build on original graph ----
    k_zero_int<<<(n0 + TB - 1) / TB, TB>>>(degP, n0);
    k_count<<<EB, TB>>>(ei + E, E, degP);
    k_scan1<<<64, 1024>>>(degP, partP);
    k_scan2<<<1, 64>>>(partP, offsP);
    k_scan3<<<64, 1024>>>(degP, offsP, rpP, curP, n0);
    k_scatter<<<EB, TB>>>(ei, ei + E, E, curP, nbrP);
    k_initmaps<<<(n0 + TB - 1) / TB, TB>>>(o2cP, c2oP);

    struct LayerCfg {
        const float *xin, *Wl, *bl, *Wr, *pw;
        float* pool;
        int n, Npg, K, round;
    };
    LayerCfg layers[3] = {
        { x,     Wl1, bl1, Wr1, pw1, poolA, BGR * NPG0, NPG0, K1, 0 },
        { poolA, Wl2, bl2, Wr2, pw2, poolB, BGR * K1,   K1,   K2, 1 },
        { poolB, Wl3, bl3, Wr3, pw3, poolA, BGR * K2,   K2,   K3, 2 },
    };

    for (int L = 0; L < 3; L++) {
        LayerCfg& c = layers[L];
        int n = c.n;
        k_splitB<<<128, 256>>>(c.Wl, c.Wr, bhiP, bloP);
        if (L == 0)
            k_aggregate1<<<(n * 32 + TB - 1) / TB, TB>>>(c.xin, rpP, nbrP, meanP, n);
        else
            k_aggregate<<<(n * 32 + TB - 1) / TB, TB>>>(c.xin, rpP, nbrP, c2oP, o2cP, meanP, n);
        k_gemm_mma<<<n / 128, 256>>>(meanP, c.xin, bhiP, bloP, c.bl, hP, n);
        k_score<<<(n * 32 + TB - 1) / TB, TB>>>(hP, c.pw, scoreP, n);
        k_topk<<<BGR, 1024>>>(scoreP, hP, c.pool, newidP, sP, c.Npg, c.K, c.round);
        if (L < 2) k_compose<<<(n0 + TB - 1) / TB, TB>>>(o2cP, c2oP, newidP);
    }

    k_mlp<<<BGR, 128>>>(sP, W1, b1, W2, b2, W3, b3, (float*)d_out);
}